// round 7
// baseline (speedup 1.0000x reference)
#include <cuda_runtime.h>
#include <cuda_bf16.h>

#define BS   8
#define SEQ  2048
#define DIN  2048
#define DOUT 2048
#define RK   8
#define SCALING 2.0f   // 16.0 / R (folded into B registers at setup)

typedef unsigned long long u64;

// ---- f32x2 packed-math helpers (sm_100+) -----------------------------------
__device__ __forceinline__ u64 ffma2(u64 a, u64 b, u64 c) {
    u64 d;
    asm("fma.rn.f32x2 %0, %1, %2, %3;" : "=l"(d) : "l"(a), "l"(b), "l"(c));
    return d;
}
__device__ __forceinline__ u64 addx2(u64 a, u64 b) {
    u64 d;
    asm("add.rn.f32x2 %0, %1, %2;" : "=l"(d) : "l"(a), "l"(b));
    return d;
}
__device__ __forceinline__ u64 rep2(float x) {
    u64 r; asm("mov.b64 %0, {%1, %1};" : "=l"(r) : "f"(x)); return r;
}
__device__ __forceinline__ u64 pk2(float lo, float hi) {
    u64 r; asm("mov.b64 %0, {%1, %2};" : "=l"(r) : "f"(lo), "f"(hi)); return r;
}
__device__ __forceinline__ void upk2(u64 v, float& lo, float& hi) {
    asm("mov.b64 {%0, %1}, %2;" : "=f"(lo), "=f"(hi) : "l"(v));
}

// ---------------------------------------------------------------------------
// Single fused kernel.
// Prologue: iter-0 x prefetch -> gate MLP (smem, short chains) -> build A,B
// register slices directly from Wa/Wb (L2-resident).
// Main loop (4 rows/iter): p1 FFMA2 -> packed u64 butterfly -> STS.64 ->
// BAR1 -> warp0 builds xa_rep ({v,v} pairs) -> BAR2 -> p2 FFMA2 from LDS.128.
// ---------------------------------------------------------------------------
__global__ __launch_bounds__(512, 1) void k_main(
    const float* __restrict__ x, float* __restrict__ out,
    const float* __restrict__ ctr, const float* __restrict__ gamma,
    const float* __restrict__ beta, const float* __restrict__ W1,
    const float* __restrict__ b1, const float* __restrict__ W2,
    const float* __restrict__ b2, const float* __restrict__ Wa,
    const float* __restrict__ Wb)
{
    const int b = blockIdx.y;
    const int tid = threadIdx.x;
    const int warp = tid >> 5, lane = tid & 31;
    const int d0 = tid * 4;

    __shared__ float zs[32];
    __shared__ float hs[64];
    __shared__ float graw[4];
    __shared__ u64 part[16][16];
    __shared__ u64 xa_rep[32];    // {v, v} replicated pairs, index = rr*8 + r

    const float* xb = x + (size_t)b * SEQ * DIN;
    float* ob = out + (size_t)b * SEQ * DOUT;
    const int step = gridDim.x;

    // ---- iter-0 x prefetch (independent of everything) ----
    float4 xv[4];
    int q = blockIdx.x;
    {
        const int s = q * 4;
        #pragma unroll
        for (int rr = 0; rr < 4; rr++)
            xv[rr] = __ldcs((const float4*)(xb + (size_t)(s + rr) * DIN + d0));
    }

    // ---- gate MLP (per-CTA recompute; short smem chains) ----
    if (tid < 32) {
        float v = ctr[b * 32 + tid];
        float s = v;
        #pragma unroll
        for (int o = 16; o; o >>= 1) s += __shfl_xor_sync(0xffffffffu, s, o);
        float mu = s * (1.0f / 32.0f);
        float dv = v - mu;
        float s2 = dv * dv;
        #pragma unroll
        for (int o = 16; o; o >>= 1) s2 += __shfl_xor_sync(0xffffffffu, s2, o);
        zs[tid] = dv * rsqrtf(s2 * (1.0f / 32.0f) + 1e-5f) * gamma[tid] + beta[tid];
    }
    __syncthreads();
    if (tid < 64) {
        float h = 0.0f;
        if (tid < 60) {
            h = b1[tid];
            #pragma unroll
            for (int c = 0; c < 32; c++) h = fmaf(zs[c], W1[tid * 32 + c], h);
            h = fmaxf(h, 0.0f);
        }
        hs[tid] = h;
    }
    __syncthreads();
    if (tid < 4) {
        float s = b2[tid];
        #pragma unroll
        for (int j = 0; j < 60; j++) s = fmaf(hs[j], W2[tid * 60 + j], s);
        graw[tid] = s;
    }
    __syncthreads();
    if (tid < 4) {
        float m = fmaxf(fmaxf(graw[0], graw[1]), fmaxf(graw[2], graw[3]));
        float den = expf(graw[0] - m) + expf(graw[1] - m) +
                    expf(graw[2] - m) + expf(graw[3] - m);
        hs[tid] = expf(graw[tid] - m) / den;
    }
    __syncthreads();
    const float g0 = hs[0], g1 = hs[1], g2 = hs[2], g3 = hs[3];

    // ---- build A slice in regs (from Wa, L2-hot after first CTAs) ----
    // a2[j][rp] = { A[rp][d0+j], A[rp+4][d0+j] }
    u64 a2[4][4];
    #pragma unroll
    for (int j = 0; j < 4; j++) {
        float at[8];
        #pragma unroll
        for (int r = 0; r < 8; r++) {
            float4 w = *(const float4*)(Wa + ((size_t)(r * DIN + d0 + j) << 2));
            at[r] = g0 * w.x + g1 * w.y + g2 * w.z + g3 * w.w;
        }
        #pragma unroll
        for (int rp = 0; rp < 4; rp++) a2[j][rp] = pk2(at[rp], at[rp + 4]);
    }
    // ---- build B slice in regs (pre-scaled): b2r[r][0]={B[r][d0],B[r][d0+2]},
    //      b2r[r][1]={B[r][d0+1],B[r][d0+3]} ----
    u64 b2r[8][2];
    #pragma unroll
    for (int r = 0; r < 8; r++) {
        float bm[4];
        #pragma unroll
        for (int k = 0; k < 4; k++) {
            float4 w = *(const float4*)(Wb + ((size_t)(r * DOUT + d0 + k) << 2));
            bm[k] = SCALING * (g0 * w.x + g1 * w.y + g2 * w.z + g3 * w.w);
        }
        b2r[r][0] = pk2(bm[0], bm[2]);
        b2r[r][1] = pk2(bm[1], bm[3]);
    }

    // ---- main loop ----
    for (; q < SEQ / 4; q += step) {
        const int s = q * 4;

        // phase 1: acc2[v], v = rr*4+rp, packing scalars (rr*8+rp, rr*8+rp+4)
        u64 acc2[16];
        #pragma unroll
        for (int v = 0; v < 16; v++) acc2[v] = 0ull;

        #pragma unroll
        for (int rr = 0; rr < 4; rr++) {
            const float* xr = (const float*)&xv[rr];
            #pragma unroll
            for (int j = 0; j < 4; j++) {
                u64 xj2 = rep2(xr[j]);
                #pragma unroll
                for (int rp = 0; rp < 4; rp++)
                    acc2[rr * 4 + rp] = ffma2(xj2, a2[j][rp], acc2[rr * 4 + rp]);
            }
        }

        // prefetch next iteration's rows (xv dead now)
        const int qn = q + step;
        if (qn < SEQ / 4) {
            const int sn = qn * 4;
            #pragma unroll
            for (int rr = 0; rr < 4; rr++)
                xv[rr] = __ldcs((const float4*)(xb + (size_t)(sn + rr) * DIN + d0));
        }

        // packed butterfly: 16 u64 values over 16-lane halves, then cross-half.
        // After: lanes l and l^16 hold warp-total of value (l & 15).
        #pragma unroll
        for (int off = 8; off >= 1; off >>= 1) {
            const bool up = (lane & off) != 0;
            #pragma unroll
            for (int i = 0; i < off; i++) {
                u64 send = up ? acc2[i] : acc2[off + i];
                u64 recv = __shfl_xor_sync(0xffffffffu, send, off);
                u64 keep = up ? acc2[off + i] : acc2[i];
                acc2[i] = addx2(keep, recv);
            }
        }
        acc2[0] = addx2(acc2[0], __shfl_xor_sync(0xffffffffu, acc2[0], 16));

        if (lane < 16) part[warp][lane] = acc2[0];
        __syncthreads();

        // warp 0: cross-warp sum + build replicated pairs
        if (warp == 0 && lane < 16) {
            const int m = lane;
            u64 s0 = addx2(part[0][m], part[1][m]);
            u64 s1 = addx2(part[2][m], part[3][m]);
            u64 s2 = addx2(part[4][m], part[5][m]);
            u64 s3 = addx2(part[6][m], part[7][m]);
            u64 s4 = addx2(part[8][m], part[9][m]);
            u64 s5 = addx2(part[10][m], part[11][m]);
            u64 s6 = addx2(part[12][m], part[13][m]);
            u64 s7 = addx2(part[14][m], part[15][m]);
            u64 t = addx2(addx2(addx2(s0, s1), addx2(s2, s3)),
                          addx2(addx2(s4, s5), addx2(s6, s7)));
            float lo, hi;
            upk2(t, lo, hi);
            const int sc = (m >> 2) * 8 + (m & 3);   // scalar index rr*8 + rp
            xa_rep[sc]     = pk2(lo, lo);
            xa_rep[sc + 4] = pk2(hi, hi);
        }
        __syncthreads();

        // phase 2: out rows from xa_rep pairs (broadcast LDS.128) + B regs
        #pragma unroll
        for (int rr = 0; rr < 4; rr++) {
            u64 o20 = 0ull, o21 = 0ull;
            #pragma unroll
            for (int rp = 0; rp < 4; rp++) {
                ulonglong2 xp = *(const ulonglong2*)&xa_rep[rr * 8 + rp * 2];
                o20 = ffma2(xp.x, b2r[2 * rp][0], o20);
                o21 = ffma2(xp.x, b2r[2 * rp][1], o21);
                o20 = ffma2(xp.y, b2r[2 * rp + 1][0], o20);
                o21 = ffma2(xp.y, b2r[2 * rp + 1][1], o21);
            }
            float o0, o1, o2s, o3;
            upk2(o20, o0, o2s);
            upk2(o21, o1, o3);
            __stcs((float4*)(ob + (size_t)(s + rr) * DOUT + d0),
                   make_float4(o0, o1, o2s, o3));
        }
    }
}

// ---------------------------------------------------------------------------
extern "C" void kernel_launch(void* const* d_in, const int* in_sizes, int n_in,
                              void* d_out, int out_size)
{
    const float* x     = (const float*)d_in[0];
    const float* ctr   = (const float*)d_in[1];
    const float* gamma = (const float*)d_in[2];
    const float* beta  = (const float*)d_in[3];
    const float* W1    = (const float*)d_in[4];
    const float* b1    = (const float*)d_in[5];
    const float* W2    = (const float*)d_in[6];
    const float* b2    = (const float*)d_in[7];
    const float* Wa    = (const float*)d_in[8];
    const float* Wb    = (const float*)d_in[9];
    float* out = (float*)d_out;

    k_main<<<dim3(18, 8), 512>>>(x, out, ctr, gamma, beta, W1, b1, W2, b2, Wa, Wb);
}